// round 7
// baseline (speedup 1.0000x reference)
#include <cuda_runtime.h>

#define NN 100000
#define NE 600000
#define NG 512
#define FD 128
#define SCAN_B 1024
#define NB_SCAN ((NN + SCAN_B - 1) / SCAN_B)   // 98

// Scratch (allocation-free rule: __device__ globals). No float atomics anywhere.
__device__ float g_hw [NN * FD];   // h @ W
__device__ float g_agg[NN * FD];   // aggregated layer output
__device__ float g_dis[NN];        // deg^{-1/2}
__device__ int   g_deg[NN];        // in-degree (excluding self loop)
__device__ int   g_scan[NN];       // inclusive per-block scan
__device__ int   g_bsum[NB_SCAN];
__device__ int   g_boff[NB_SCAN];
__device__ int   g_rowstart[NN];   // CSR row starts (exclusive scan)
__device__ int   g_cursor[NN];     // fill cursors
__device__ int   g_csrc[NE];       // CSR: src lists grouped by dst
__device__ int   g_gstart[NG + 1]; // graph segment starts (batch is sorted)

// ---------------------------------------------------------------------------
__global__ void k_zero() {
    int i = blockIdx.x * blockDim.x + threadIdx.x;
    if (i < NN) g_deg[i] = 0;
}

// in-degree count over edge dst (int atomics only). ei is int32: [src[NE], dst[NE]]
__global__ void k_count(const int* __restrict__ ei) {
    int e = blockIdx.x * blockDim.x + threadIdx.x;
    if (e < NE) atomicAdd(&g_deg[ei[NE + e]], 1);
}

// per-1024-block inclusive scan of g_deg
__global__ void __launch_bounds__(SCAN_B) k_scan1() {
    __shared__ int s[SCAN_B];
    int tid = threadIdx.x;
    int i = blockIdx.x * SCAN_B + tid;
    s[tid] = (i < NN) ? g_deg[i] : 0;
    __syncthreads();
#pragma unroll
    for (int off = 1; off < SCAN_B; off <<= 1) {
        int v = (tid >= off) ? s[tid - off] : 0;
        __syncthreads();
        s[tid] += v;
        __syncthreads();
    }
    if (i < NN) g_scan[i] = s[tid];
    if (tid == SCAN_B - 1) g_bsum[blockIdx.x] = s[tid];
}

// scan the block sums (trivial size)
__global__ void k_scan2() {
    int run = 0;
    for (int b = 0; b < NB_SCAN; b++) { g_boff[b] = run; run += g_bsum[b]; }
}

// finalize: exclusive row starts, cursors, and normalization dis = rsqrt(1+deg)
__global__ void k_scan3() {
    int i = blockIdx.x * blockDim.x + threadIdx.x;
    if (i < NN) {
        int excl = g_scan[i] + g_boff[i >> 10] - g_deg[i];
        g_rowstart[i] = excl;
        g_cursor[i]   = excl;
        g_dis[i] = rsqrtf(1.0f + (float)g_deg[i]);
    }
}

// CSR fill
__global__ void k_fill(const int* __restrict__ ei) {
    int e = blockIdx.x * blockDim.x + threadIdx.x;
    if (e < NE) {
        int s = ei[e];
        int d = ei[NE + e];
        int pos = atomicAdd(&g_cursor[d], 1);
        g_csrc[pos] = s;
    }
}

// graph segment starts from SORTED batch: gstart[g] = first n with batch[n] >= g
__global__ void k_gstart(const int* __restrict__ batch) {
    int i = blockIdx.x * blockDim.x + threadIdx.x;
    if (i <= NN) {
        int prev = (i == 0) ? -1 : batch[i - 1];
        int cur  = (i < NN) ? batch[i] : NG;
        for (int g = prev + 1; g <= cur; g++) g_gstart[g] = i;
    }
}

// ---------------------------------------------------------------------------
// GEMM: Out[NN,128] = f(A)[NN,128] @ W[128,128]
// f(A) = A (layer 1) or relu(A + bias) (layer 2 input transform)
template <bool RELU_BIAS>
__global__ void __launch_bounds__(256) k_gemm(
    const float* __restrict__ A, const float* __restrict__ W,
    const float* __restrict__ bias, float* __restrict__ Out)
{
    __shared__ float Xs[32][68];    // [k][row]; stride 272B keeps float4 align
    __shared__ float Ws[32][128];   // [k][col]

    const int block_row = blockIdx.x * 64;
    const int tid = threadIdx.x;
    const int tr = tid >> 4;        // 0..15  row group (4 rows each)
    const int tc = tid & 15;        // 0..15  col group (8 cols each)

    float acc[4][8];
#pragma unroll
    for (int i = 0; i < 4; i++)
#pragma unroll
        for (int j = 0; j < 8; j++) acc[i][j] = 0.0f;

    for (int k0 = 0; k0 < FD; k0 += 32) {
        for (int i = tid; i < 64 * 32; i += 256) {
            int r = i >> 5, c = i & 31;
            int row = block_row + r;
            float v = 0.0f;
            if (row < NN) {
                v = A[row * FD + k0 + c];
                if (RELU_BIAS) v = fmaxf(v + bias[k0 + c], 0.0f);
            }
            Xs[c][r] = v;
        }
        for (int i = tid; i < 32 * 128; i += 256) {
            int r = i >> 7, c = i & 127;
            Ws[r][c] = W[(k0 + r) * FD + c];
        }
        __syncthreads();

#pragma unroll
        for (int k = 0; k < 32; k++) {
            float4 a4 = *reinterpret_cast<const float4*>(&Xs[k][tr * 4]);
            float4 b0 = *reinterpret_cast<const float4*>(&Ws[k][tc * 8]);
            float4 b1 = *reinterpret_cast<const float4*>(&Ws[k][tc * 8 + 4]);
            float a[4] = {a4.x, a4.y, a4.z, a4.w};
            float b[8] = {b0.x, b0.y, b0.z, b0.w, b1.x, b1.y, b1.z, b1.w};
#pragma unroll
            for (int i = 0; i < 4; i++)
#pragma unroll
                for (int j = 0; j < 8; j++) acc[i][j] += a[i] * b[j];
        }
        __syncthreads();
    }

#pragma unroll
    for (int i = 0; i < 4; i++) {
        int row = block_row + tr * 4 + i;
        if (row < NN) {
            float4 o0 = make_float4(acc[i][0], acc[i][1], acc[i][2], acc[i][3]);
            float4 o1 = make_float4(acc[i][4], acc[i][5], acc[i][6], acc[i][7]);
            *reinterpret_cast<float4*>(&Out[row * FD + tc * 8])     = o0;
            *reinterpret_cast<float4*>(&Out[row * FD + tc * 8 + 4]) = o1;
        }
    }
}

// ---------------------------------------------------------------------------
// CSR gather aggregation: warp per dst node, lane = one float4 of features.
// agg[d] = dis[d]^2 * hw[d] + dis[d] * sum_{s in adj(d)} dis[s] * hw[s]
__global__ void k_gather() {
    int gid = blockIdx.x * blockDim.x + threadIdx.x;
    int n = gid >> 5;
    int lane = gid & 31;
    if (n >= NN) return;

    const float4* hw4 = reinterpret_cast<const float4*>(g_hw);
    int start = g_rowstart[n];
    int cnt   = g_deg[n];

    float4 acc = make_float4(0.f, 0.f, 0.f, 0.f);
    for (int j = 0; j < cnt; j++) {
        int s = g_csrc[start + j];          // broadcast load across warp
        float w = g_dis[s];
        float4 v = hw4[s * 32 + lane];
        acc.x += w * v.x; acc.y += w * v.y;
        acc.z += w * v.z; acc.w += w * v.w;
    }
    float dd = g_dis[n];
    float w2 = dd * dd;
    float4 self = hw4[n * 32 + lane];
    float4 o = make_float4(dd * acc.x + w2 * self.x,
                           dd * acc.y + w2 * self.y,
                           dd * acc.z + w2 * self.z,
                           dd * acc.w + w2 * self.w);
    reinterpret_cast<float4*>(g_agg)[n * 32 + lane] = o;
}

// ---------------------------------------------------------------------------
// pooling over contiguous graph segments + readout, fused. Block per graph.
__global__ void __launch_bounds__(128) k_pool_final(
    const float* __restrict__ b2, const float* __restrict__ Wlin,
    const float* __restrict__ blin, float* __restrict__ out)
{
    __shared__ float sh[128];
    int g = blockIdx.x;
    int f = threadIdx.x;
    int n0 = g_gstart[g], n1 = g_gstart[g + 1];
    int cnt = n1 - n0;

    float acc = 0.0f;
    for (int n = n0; n < n1; n++) acc += g_agg[n * FD + f];

    float inv = (cnt > 0) ? 1.0f / (float)cnt : 0.0f;
    float pooled = acc * inv + ((cnt > 0) ? b2[f] : 0.0f);
    sh[f] = pooled * Wlin[f];
    __syncthreads();
#pragma unroll
    for (int off = 64; off > 0; off >>= 1) {
        if (f < off) sh[f] += sh[f + off];
        __syncthreads();
    }
    if (f == 0) out[g] = sh[0] + blin[0];
}

// ---------------------------------------------------------------------------
extern "C" void kernel_launch(void* const* d_in, const int* in_sizes, int n_in,
                              void* d_out, int out_size)
{
    const float* x     = (const float*)d_in[0];
    const int*   ei    = (const int*)d_in[1];     // int32 (harness casts int64 -> int32)
    const int*   batch = (const int*)d_in[2];     // int32
    const float* W1    = (const float*)d_in[3];
    const float* b1    = (const float*)d_in[4];
    const float* W2    = (const float*)d_in[5];
    const float* b2    = (const float*)d_in[6];
    const float* Wlin  = (const float*)d_in[7];
    const float* blin  = (const float*)d_in[8];
    float* out = (float*)d_out;

    void *p_hw, *p_agg;
    cudaGetSymbolAddress(&p_hw,  g_hw);
    cudaGetSymbolAddress(&p_agg, g_agg);
    float* hw  = (float*)p_hw;
    float* agg = (float*)p_agg;

    const int T = 256;
    const int nn_blocks   = (NN + T - 1) / T;
    const int ne_blocks   = (NE + T - 1) / T;
    const int gemm_blocks = (NN + 63) / 64;
    const int gat_blocks  = (NN * 32 + T - 1) / T;

    // CSR build + normalization + graph segments
    k_zero  <<<nn_blocks, T>>>();
    k_count <<<ne_blocks, T>>>(ei);
    k_scan1 <<<NB_SCAN, SCAN_B>>>();
    k_scan2 <<<1, 1>>>();
    k_scan3 <<<nn_blocks, T>>>();
    k_fill  <<<ne_blocks, T>>>(ei);
    k_gstart<<<(NN + 1 + T - 1) / T, T>>>(batch);

    // Layer 1: hw = x @ W1 ; agg = A_norm @ hw (bias+relu folded into gemm2 load)
    k_gemm<false><<<gemm_blocks, T>>>(x, W1, nullptr, hw);
    k_gather     <<<gat_blocks, T>>>();

    // Layer 2: hw = relu(agg + b1) @ W2 ; agg = A_norm @ hw
    k_gemm<true> <<<gemm_blocks, T>>>(agg, W2, b1, hw);
    k_gather     <<<gat_blocks, T>>>();

    // Mean-pool (contiguous segments) + readout, b2 folded with empty-graph guard
    k_pool_final <<<NG, 128>>>(b2, Wlin, blin, out);
}